// round 11
// baseline (speedup 1.0000x reference)
#include <cuda_runtime.h>
#include <cuda_bf16.h>
#include <math.h>

#define BB 8
#define NN 4096
#define CC 64
#define NPOINT 1024
#define KK 32
#define MM (BB*NPOINT)
#define RR (MM*KK)
#define EPSBN 1e-5f
#define SLOPE 0.1f

typedef unsigned long long u64;
typedef unsigned int u32;
typedef unsigned short u16;

__device__ float g_buf[4][RR*CC];      // 0:y_t 1:y1/y3 2:y2 3:y4
__device__ int   g_fps[MM];
__device__ int   g_knn[RR];
__device__ float g_pn[BB*NN];
__device__ float g_part[2048][2][CC];
__device__ float g_aff[5][2][CC];

__device__ __forceinline__ float leaky(float x){ return x>=0.f ? x : SLOPE*x; }

// ---- packed f32x2 (bitwise == two scalar rn ops) ----
#define ADD2(o,a,b) asm("add.rn.f32x2 %0,%1,%2;":"=l"(o):"l"(a),"l"(b))
#define MUL2(o,a,b) asm("mul.rn.f32x2 %0,%1,%2;":"=l"(o):"l"(a),"l"(b))
#define PACK2(o,lo,hi) asm("mov.b64 %0,{%1,%2};":"=l"(o):"f"(lo),"f"(hi))
#define UNPK2(lo,hi,i) asm("mov.b64 {%0,%1},%2;":"=f"(lo),"=f"(hi):"l"(i))

// ---------------- per-point squared norms (ref order) ----------------
__global__ void pnorm_kernel(const float* __restrict__ xyz){
    int i = blockIdx.x*blockDim.x + threadIdx.x;
    if (i < BB*NN){
        float x = xyz[3*i], y = xyz[3*i+1], z = xyz[3*i+2];
        g_pn[i] = __fadd_rn(__fadd_rn(__fmul_rn(x,x), __fmul_rn(y,y)), __fmul_rn(z,z));
    }
}

// ---------------- FPS: 1 block/batch, 256 thr, 16 pts/thr ---------------
// Bit-exact reference semantics (x-c == x+(-c) exactly; u32 order == f32
// order on non-negative values; ~index max == first-index tie-break).
__global__ void __launch_bounds__(256)
fps_kernel(const float* __restrict__ xyz, float* __restrict__ out){
    __shared__ u64 swk[2][8];
    int b=blockIdx.x, tid=threadIdx.x, lane=tid&31, wid=tid>>5;
    const float* g = xyz + b*NN*3;

    u64 px[8], py[8], pz[8];
    float pd[16];
#pragma unroll
    for (int q=0;q<8;++q){
        int j0 = tid + 512*q, j1 = j0 + 256;
        float x0=g[3*j0], x1=g[3*j1];
        float y0=g[3*j0+1], y1=g[3*j1+1];
        float z0=g[3*j0+2], z1=g[3*j1+2];
        PACK2(px[q],x0,x1); PACK2(py[q],y0,y1); PACK2(pz[q],z0,z1);
        pd[2*q]=1e10f; pd[2*q+1]=1e10f;
    }
    if (tid==0){
        g_fps[b*NPOINT] = 0;
        out[b*3*NPOINT + 0*NPOINT] = g[0];
        out[b*3*NPOINT + 1*NPOINT] = g[1];
        out[b*3*NPOINT + 2*NPOINT] = g[2];
    }
    float cx=g[0], cy=g[1], cz=g[2];

    for (int t=1; t<NPOINT; ++t){
        float nx=__int_as_float(__float_as_int(cx)^0x80000000);
        float ny=__int_as_float(__float_as_int(cy)^0x80000000);
        float nz=__int_as_float(__float_as_int(cz)^0x80000000);
        u64 ncx,ncy,ncz; PACK2(ncx,nx,nx); PACK2(ncy,ny,ny); PACK2(ncz,nz,nz);
#pragma unroll
        for (int q=0;q<8;++q){
            u64 dx,dy,dz,s01,dv;
            ADD2(dx,px[q],ncx); ADD2(dy,py[q],ncy); ADD2(dz,pz[q],ncz);
            MUL2(dx,dx,dx); MUL2(dy,dy,dy); MUL2(dz,dz,dz);
            ADD2(s01,dx,dy); ADD2(dv,s01,dz);
            float d0,d1; UNPK2(d0,d1,dv);
            pd[2*q]   = fminf(pd[2*q],   d0);
            pd[2*q+1] = fminf(pd[2*q+1], d1);
        }
        float m0=pd[0], m1=pd[1], m2=pd[2], m3=pd[3];
#pragma unroll
        for (int i=4;i<16;i+=4){
            m0=fmaxf(m0,pd[i]); m1=fmaxf(m1,pd[i+1]);
            m2=fmaxf(m2,pd[i+2]); m3=fmaxf(m3,pd[i+3]);
        }
        float bv = fmaxf(fmaxf(m0,m1), fmaxf(m2,m3));

        unsigned vb   = (unsigned)__float_as_int(bv);
        unsigned vmax = __reduce_max_sync(0xffffffffu, vb);
        unsigned lo = 0u;
        if (vb == vmax){
            int bj = 0;
#pragma unroll
            for (int i=15;i>=0;--i) if (pd[i]==bv) bj = tid + 256*i;
            lo = ~(unsigned)bj;
        }
        unsigned lmax = __reduce_max_sync(0xffffffffu, lo);
        if (lane==0) swk[t&1][wid] = ((u64)vmax<<32) | lmax;
        __syncthreads();

        u64 k = swk[t&1][lane&7];
        unsigned hi  = (unsigned)(k>>32);
        unsigned hm  = __reduce_max_sync(0xffffffffu, hi);
        unsigned lo2 = (hi==hm) ? (unsigned)k : 0u;
        unsigned lm  = __reduce_max_sync(0xffffffffu, lo2);
        int far = (int)(~lm);
        cx = __ldg(&g[3*far]); cy = __ldg(&g[3*far+1]); cz = __ldg(&g[3*far+2]);
        if (tid==0){
            g_fps[b*NPOINT + t] = far;
            out[b*3*NPOINT + 0*NPOINT + t] = cx;
            out[b*3*NPOINT + 1*NPOINT + t] = cy;
            out[b*3*NPOINT + 2*NPOINT + t] = cz;
        }
    }
}

// ---------------- kNN: one warp per query, streaming top-32 -------------
__device__ __forceinline__ void warp_argmax(float& mv, int& ml){
#pragma unroll
    for (int off=16; off; off>>=1){
        float ov = __shfl_xor_sync(0xffffffffu, mv, off);
        int   ol = __shfl_xor_sync(0xffffffffu, ml, off);
        if (ov > mv || (ov == mv && ol < ml)){ mv = ov; ml = ol; }
    }
}

__global__ void __launch_bounds__(256)
knn_kernel(const float* __restrict__ xyz){
    int wid  = threadIdx.x >> 5, lane = threadIdx.x & 31;
    int b = blockIdx.x >> 7;
    int s = ((blockIdx.x & 127) << 3) + wid;
    const float* xb  = xyz + b*NN*3;
    const float* pnb = g_pn + b*NN;

    int qidx = g_fps[b*NPOINT + s];
    float qx = xb[3*qidx], qy = xb[3*qidx+1], qz = xb[3*qidx+2];
    float qn = pnb[qidx];

    float v; int vi;
    {
        int j = lane;
        float dot = __fadd_rn(__fadd_rn(__fmul_rn(qx,xb[3*j]), __fmul_rn(qy,xb[3*j+1])),
                              __fmul_rn(qz,xb[3*j+2]));
        v  = __fadd_rn(__fadd_rn(__fmul_rn(-2.f,dot), qn), pnb[j]);
        vi = j;
    }
    float mv = v; int ml = lane;
    warp_argmax(mv, ml);
    float tau = mv; int maxlane = ml;

    for (int base=32; base<NN; base+=32){
        int j = base + lane;
        float dot = __fadd_rn(__fadd_rn(__fmul_rn(qx,xb[3*j]), __fmul_rn(qy,xb[3*j+1])),
                              __fmul_rn(qz,xb[3*j+2]));
        float cand = __fadd_rn(__fadd_rn(__fmul_rn(-2.f,dot), qn), pnb[j]);
        unsigned mask = __ballot_sync(0xffffffffu, cand < tau);
        while (mask){
            int src  = __ffs(mask) - 1;
            float cv = __shfl_sync(0xffffffffu, cand, src);
            if (lane == maxlane){ v = cv; vi = base + src; }
            if (lane == src) cand = 3.0e38f;
            mv = v; ml = lane;
            warp_argmax(mv, ml);
            tau = mv; maxlane = ml;
            mask = __ballot_sync(0xffffffffu, cand < tau);
        }
    }
    g_knn[(b*NPOINT + s)*KK + lane] = vi;
}

// ---------------- conv via mma.sync bf16 3-pass (hi/lo split) -----------
// y[r][o] = sum_c x[r][c]*W[o][c], 128 rows x 64 outs per block, 256 thr.
// smem (ushort elems): Xh[128][72]@0, Xl@9216, Wh[64][72]@18432, Wl@23040.
// Stats overlay: fp32 ys[128][65] over Xh/Xl; sred over W region.
#define XP 72
#define CONV_SMEM 55296

__device__ __forceinline__ void mma_bf16(float* d, const u32* a, const u32* bfr){
    asm volatile("mma.sync.aligned.m16n8k16.row.col.f32.bf16.bf16.f32 "
        "{%0,%1,%2,%3},{%4,%5,%6,%7},{%8,%9},{%0,%1,%2,%3};"
        : "+f"(d[0]),"+f"(d[1]),"+f"(d[2]),"+f"(d[3])
        : "r"(a[0]),"r"(a[1]),"r"(a[2]),"r"(a[3]),"r"(bfr[0]),"r"(bfr[1]));
}
__device__ __forceinline__ u32 bfsplit(float v, float& rem){
    __nv_bfloat16 h = __float2bfloat16_rn(v);
    rem = v - __bfloat162float(h);
    return (u32)__bfloat16_as_ushort(h);
}

template<int MODE>
__global__ void __launch_bounds__(256)
conv_kernel(int i0, int i1, const float* __restrict__ W,
            const float* __restrict__ features, int oid, int affA, int affB){
    extern __shared__ char smraw[];
    u16* Xh = (u16*)smraw;
    u16* Xl = Xh + 128*XP;
    u16* Wh = Xl + 128*XP;
    u16* Wl = Wh + 64*XP;

    const int tid = threadIdx.x;
    const int rbase = blockIdx.x * 128;

    for (int i=tid; i<4096; i+=256){
        int o=i>>6, c=i&63;
        float rem;
        u32 h = bfsplit(W[i], rem);
        Wh[o*XP+c] = (u16)h;
        Wl[o*XP+c] = __bfloat16_as_ushort(__float2bfloat16_rn(rem));
    }
    for (int i=tid; i<4096; i+=256){
        int row=i>>5, cp=(i&31)*2;
        int r = rbase + row;
        float v0, v1;
        if (MODE==0){
            int idx = g_knn[r]; int bb = r>>15;
            const float2 f = *(const float2*)&features[((size_t)((bb<<12)+idx))*CC + cp];
            v0=f.x; v1=f.y;
        } else {
            const float2 x0 = *(const float2*)&g_buf[i0][(size_t)r*CC + cp];
            float a10=g_aff[affB][0][cp], a11=g_aff[affB][0][cp+1];
            float d10=g_aff[affB][1][cp], d11=g_aff[affB][1][cp+1];
            if (MODE==1){
                v0 = leaky(fmaf(a10,x0.x,d10));
                v1 = leaky(fmaf(a11,x0.y,d11));
            } else {
                const float2 x1 = *(const float2*)&g_buf[i1][(size_t)r*CC + cp];
                float a00=g_aff[affA][0][cp], a01=g_aff[affA][0][cp+1];
                float d00=g_aff[affA][1][cp], d01=g_aff[affA][1][cp+1];
                v0 = leaky(fmaf(a10,x0.x,d10) + leaky(fmaf(a00,x1.x,d00)));
                v1 = leaky(fmaf(a11,x0.y,d11) + leaky(fmaf(a01,x1.y,d01)));
            }
        }
        float r0,r1;
        u32 h0 = bfsplit(v0,r0), h1 = bfsplit(v1,r1);
        Xh[row*XP+cp]   = (u16)h0;
        Xh[row*XP+cp+1] = (u16)h1;
        Xl[row*XP+cp]   = __bfloat16_as_ushort(__float2bfloat16_rn(r0));
        Xl[row*XP+cp+1] = __bfloat16_as_ushort(__float2bfloat16_rn(r1));
    }
    __syncthreads();

    const int wid = tid>>5, lane = tid&31;
    const int wm = wid>>1, wn = wid&1;         // 4 m-warps x 2 n-warps
    const int m0 = wm*32, n0 = wn*32;
    const int lr = lane>>2, lc = (lane&3)*2;

    float acc[2][4][4];
#pragma unroll
    for (int mt=0;mt<2;++mt)
#pragma unroll
        for (int nt=0;nt<4;++nt)
#pragma unroll
            for (int q=0;q<4;++q) acc[mt][nt][q]=0.f;

#pragma unroll
    for (int pass=0; pass<3; ++pass){
        const u16* Xs = (pass==2)? Xl : Xh;
        const u16* Ws = (pass==1)? Wl : Wh;
#pragma unroll
        for (int ks=0; ks<4; ++ks){
            int k0 = ks*16;
            u32 a[2][4];
#pragma unroll
            for (int mt=0;mt<2;++mt){
                int r = m0 + mt*16 + lr;
                a[mt][0] = *(const u32*)&Xs[r*XP + k0 + lc];
                a[mt][1] = *(const u32*)&Xs[(r+8)*XP + k0 + lc];
                a[mt][2] = *(const u32*)&Xs[r*XP + k0 + 8 + lc];
                a[mt][3] = *(const u32*)&Xs[(r+8)*XP + k0 + 8 + lc];
            }
            u32 bfr[4][2];
#pragma unroll
            for (int nt=0;nt<4;++nt){
                int n = n0 + nt*8 + lr;
                bfr[nt][0] = *(const u32*)&Ws[n*XP + k0 + lc];
                bfr[nt][1] = *(const u32*)&Ws[n*XP + k0 + 8 + lc];
            }
#pragma unroll
            for (int mt=0;mt<2;++mt)
#pragma unroll
                for (int nt=0;nt<4;++nt)
                    mma_bf16(acc[mt][nt], a[mt], bfr[nt]);
        }
    }
    __syncthreads();   // all fragment LDS done before overlaying smem

    // store y to gmem
    float* outb = g_buf[oid];
#pragma unroll
    for (int mt=0;mt<2;++mt){
        size_t row0 = (size_t)(rbase + m0 + mt*16 + lr);
#pragma unroll
        for (int nt=0;nt<4;++nt){
            int col = n0 + nt*8 + lc;
            *(float2*)&outb[row0*CC + col]     = make_float2(acc[mt][nt][0], acc[mt][nt][1]);
            *(float2*)&outb[(row0+8)*CC + col] = make_float2(acc[mt][nt][2], acc[mt][nt][3]);
        }
    }
    // stats via smem overlay
    float* ys = (float*)smraw;            // [128][65]
#pragma unroll
    for (int mt=0;mt<2;++mt){
        int row0 = m0 + mt*16 + lr;
#pragma unroll
        for (int nt=0;nt<4;++nt){
            int col = n0 + nt*8 + lc;
            ys[row0*65 + col]   = acc[mt][nt][0];
            ys[row0*65 + col+1] = acc[mt][nt][1];
            ys[(row0+8)*65 + col]   = acc[mt][nt][2];
            ys[(row0+8)*65 + col+1] = acc[mt][nt][3];
        }
    }
    __syncthreads();
    float* sred1 = (float*)(smraw + 36864);      // [4][64]
    float* sred2 = sred1 + 256;
    {
        int c = tid&63, h = tid>>6;
        float s1=0.f, s2=0.f;
        for (int j=h*32; j<h*32+32; ++j){ float v=ys[j*65+c]; s1+=v; s2+=v*v; }
        sred1[h*64+c]=s1; sred2[h*64+c]=s2;
    }
    __syncthreads();
    if (tid < CC){
        g_part[blockIdx.x][0][tid] = sred1[tid]+sred1[64+tid]+sred1[128+tid]+sred1[192+tid];
        g_part[blockIdx.x][1][tid] = sred2[tid]+sred2[64+tid]+sred2[128+tid]+sred2[192+tid];
    }
}

// ---------------- BN affine finalize ----------------
__global__ void __launch_bounds__(256)
affine_kernel(int stage, const float* __restrict__ gam, const float* __restrict__ bet){
    __shared__ float r1[256], r2[256];
    int c = blockIdx.x, t = threadIdx.x;
    float s1=0.f, s2=0.f;
    for (int p=t; p<2048; p+=256){ s1 += g_part[p][0][c]; s2 += g_part[p][1][c]; }
    r1[t]=s1; r2[t]=s2; __syncthreads();
    for (int off=128; off; off>>=1){
        if (t < off){ r1[t]+=r1[t+off]; r2[t]+=r2[t+off]; }
        __syncthreads();
    }
    if (t==0){
        float inv  = 1.f/(float)RR;
        float mean = r1[0]*inv;
        float var  = r2[0]*inv - mean*mean;
        float a    = gam[c]/sqrtf(var + EPSBN);
        g_aff[stage][0][c] = a;
        g_aff[stage][1][c] = bet[c] - a*mean;
    }
}

// ---------------- final: recompute x1 and max over K ----------------
__global__ void __launch_bounds__(256)
final_kernel(float* __restrict__ out){
    int tid = threadIdx.x;
    int mi = tid >> 6, c = tid & 63;
    int m = blockIdx.x*4 + mi;
    float a0=g_aff[0][0][c], d0=g_aff[0][1][c];
    float a2=g_aff[2][0][c], d2=g_aff[2][1][c];
    float a4=g_aff[4][0][c], d4=g_aff[4][1][c];
    const float* yt = g_buf[0];
    const float* y2 = g_buf[2];
    const float* y4 = g_buf[3];
    float vmax = -3.4e38f;
    int rb = m*KK;
#pragma unroll 4
    for (int k=0;k<KK;++k){
        size_t idx = (size_t)(rb+k)*CC + c;
        float xt = leaky(fmaf(a0, yt[idx], d0));
        float x0 = leaky(fmaf(a2, y2[idx], d2) + xt);
        float x1 = leaky(fmaf(a4, y4[idx], d4) + x0);
        vmax = fmaxf(vmax, x1);
    }
    int b = m >> 10, s = m & 1023;
    out[BB*3*NPOINT + (b*CC + c)*NPOINT + s] = vmax;
}

// ---------------- launch ----------------
extern "C" void kernel_launch(void* const* d_in, const int* in_sizes, int n_in,
                              void* d_out, int out_size){
    (void)n_in; (void)out_size;
    const float* xyz  = (const float*)d_in[0];
    const float* feat = (const float*)d_in[1];
    const float *w[5], *gam[5], *bet[5];
    if (in_sizes[3] == CC*CC){
        const int wi[5]={2,3,4,5,6}, gi[5]={12,13,14,15,16}, bi[5]={17,18,19,20,21};
        for (int i=0;i<5;++i){ w[i]=(const float*)d_in[wi[i]];
                               gam[i]=(const float*)d_in[gi[i]];
                               bet[i]=(const float*)d_in[bi[i]]; }
    } else {
        const int wi[5]={2,6,10,14,18}, gi[5]={4,8,12,16,20}, bi[5]={5,9,13,17,21};
        for (int i=0;i<5;++i){ w[i]=(const float*)d_in[wi[i]];
                               gam[i]=(const float*)d_in[gi[i]];
                               bet[i]=(const float*)d_in[bi[i]]; }
    }
    float* out = (float*)d_out;

    cudaFuncSetAttribute(conv_kernel<0>, cudaFuncAttributeMaxDynamicSharedMemorySize, CONV_SMEM);
    cudaFuncSetAttribute(conv_kernel<1>, cudaFuncAttributeMaxDynamicSharedMemorySize, CONV_SMEM);
    cudaFuncSetAttribute(conv_kernel<2>, cudaFuncAttributeMaxDynamicSharedMemorySize, CONV_SMEM);

    pnorm_kernel<<<128,256>>>(xyz);
    fps_kernel<<<BB,256>>>(xyz, out);
    knn_kernel<<<1024,256>>>(xyz);

    conv_kernel<0><<<2048,256,CONV_SMEM>>>(0,0,w[0],feat,0,0,0);
    affine_kernel<<<64,256>>>(0, gam[0], bet[0]);
    conv_kernel<1><<<2048,256,CONV_SMEM>>>(0,0,w[1],feat,1,0,0);
    affine_kernel<<<64,256>>>(1, gam[1], bet[1]);
    conv_kernel<1><<<2048,256,CONV_SMEM>>>(1,0,w[2],feat,2,0,1);
    affine_kernel<<<64,256>>>(2, gam[2], bet[2]);
    conv_kernel<2><<<2048,256,CONV_SMEM>>>(2,0,w[3],feat,1,0,2);
    affine_kernel<<<64,256>>>(3, gam[3], bet[3]);
    conv_kernel<1><<<2048,256,CONV_SMEM>>>(1,0,w[4],feat,3,0,3);
    affine_kernel<<<64,256>>>(4, gam[4], bet[4]);

    final_kernel<<<2048,256>>>(out);
}

// round 13
// speedup vs baseline: 1.7378x; 1.7378x over previous
#include <cuda_runtime.h>
#include <math.h>

#define BB 8
#define NN 4096
#define CC 64
#define NPOINT 1024
#define KK 32
#define MM (BB*NPOINT)
#define RR (MM*KK)          /* 262144 gathered rows */
#define UR (BB*NN)          /* 32768 unique rows    */
#define EPSBN 1e-5f
#define SLOPE 0.1f

typedef unsigned long long u64;

__device__ float g_buf[4][UR*CC];      // 0:y_t 1:y1/y3->x1 2:y2 3:y4 (8MB each)
__device__ int   g_fps[MM];
__device__ int   g_knn[RR];
__device__ float g_pn[BB*NN];
__device__ int   g_cnt[UR];
__device__ float g_part[256][2][CC];
__device__ float g_aff[5][2][CC];

__device__ __forceinline__ float leaky(float x){ return x>=0.f ? x : SLOPE*x; }

// ---- packed f32x2 (bitwise == two scalar rn ops) ----
#define ADD2(o,a,b) asm("add.rn.f32x2 %0,%1,%2;":"=l"(o):"l"(a),"l"(b))
#define MUL2(o,a,b) asm("mul.rn.f32x2 %0,%1,%2;":"=l"(o):"l"(a),"l"(b))
#define PACK2(o,lo,hi) asm("mov.b64 %0,{%1,%2};":"=l"(o):"f"(lo),"f"(hi))
#define UNPK2(lo,hi,i) asm("mov.b64 {%0,%1},%2;":"=f"(lo),"=f"(hi):"l"(i))

// ---------------- per-point squared norms (ref order) ----------------
__global__ void pnorm_kernel(const float* __restrict__ xyz){
    int i = blockIdx.x*blockDim.x + threadIdx.x;
    if (i < BB*NN){
        float x = xyz[3*i], y = xyz[3*i+1], z = xyz[3*i+2];
        g_pn[i] = __fadd_rn(__fadd_rn(__fmul_rn(x,x), __fmul_rn(y,y)), __fmul_rn(z,z));
    }
}

// ---------------- FPS: 1 block/batch, 256 thr, 16 pts/thr ---------------
__global__ void __launch_bounds__(256)
fps_kernel(const float* __restrict__ xyz, float* __restrict__ out){
    __shared__ u64 swk[2][8];
    int b=blockIdx.x, tid=threadIdx.x, lane=tid&31, wid=tid>>5;
    const float* g = xyz + b*NN*3;

    u64 px[8], py[8], pz[8];
    float pd[16];
#pragma unroll
    for (int q=0;q<8;++q){
        int j0 = tid + 512*q, j1 = j0 + 256;
        float x0=g[3*j0], x1=g[3*j1];
        float y0=g[3*j0+1], y1=g[3*j1+1];
        float z0=g[3*j0+2], z1=g[3*j1+2];
        PACK2(px[q],x0,x1); PACK2(py[q],y0,y1); PACK2(pz[q],z0,z1);
        pd[2*q]=1e10f; pd[2*q+1]=1e10f;
    }
    if (tid==0){
        g_fps[b*NPOINT] = 0;
        out[b*3*NPOINT + 0*NPOINT] = g[0];
        out[b*3*NPOINT + 1*NPOINT] = g[1];
        out[b*3*NPOINT + 2*NPOINT] = g[2];
    }
    float cx=g[0], cy=g[1], cz=g[2];

    for (int t=1; t<NPOINT; ++t){
        float nx=__int_as_float(__float_as_int(cx)^0x80000000);
        float ny=__int_as_float(__float_as_int(cy)^0x80000000);
        float nz=__int_as_float(__float_as_int(cz)^0x80000000);
        u64 ncx,ncy,ncz; PACK2(ncx,nx,nx); PACK2(ncy,ny,ny); PACK2(ncz,nz,nz);
#pragma unroll
        for (int q=0;q<8;++q){
            u64 dx,dy,dz,s01,dv;
            ADD2(dx,px[q],ncx); ADD2(dy,py[q],ncy); ADD2(dz,pz[q],ncz);
            MUL2(dx,dx,dx); MUL2(dy,dy,dy); MUL2(dz,dz,dz);
            ADD2(s01,dx,dy); ADD2(dv,s01,dz);
            float d0,d1; UNPK2(d0,d1,dv);
            pd[2*q]   = fminf(pd[2*q],   d0);
            pd[2*q+1] = fminf(pd[2*q+1], d1);
        }
        float m0=pd[0], m1=pd[1], m2=pd[2], m3=pd[3];
#pragma unroll
        for (int i=4;i<16;i+=4){
            m0=fmaxf(m0,pd[i]); m1=fmaxf(m1,pd[i+1]);
            m2=fmaxf(m2,pd[i+2]); m3=fmaxf(m3,pd[i+3]);
        }
        float bv = fmaxf(fmaxf(m0,m1), fmaxf(m2,m3));

        unsigned vb   = (unsigned)__float_as_int(bv);
        unsigned vmax = __reduce_max_sync(0xffffffffu, vb);
        unsigned lo = 0u;
        if (vb == vmax){
            int bj = 0;
#pragma unroll
            for (int i=15;i>=0;--i) if (pd[i]==bv) bj = tid + 256*i;
            lo = ~(unsigned)bj;
        }
        unsigned lmax = __reduce_max_sync(0xffffffffu, lo);
        if (lane==0) swk[t&1][wid] = ((u64)vmax<<32) | lmax;
        __syncthreads();

        u64 k = swk[t&1][lane&7];
        unsigned hi  = (unsigned)(k>>32);
        unsigned hm  = __reduce_max_sync(0xffffffffu, hi);
        unsigned lo2 = (hi==hm) ? (unsigned)k : 0u;
        unsigned lm  = __reduce_max_sync(0xffffffffu, lo2);
        int far = (int)(~lm);
        cx = __ldg(&g[3*far]); cy = __ldg(&g[3*far+1]); cz = __ldg(&g[3*far+2]);
        if (tid==0){
            g_fps[b*NPOINT + t] = far;
            out[b*3*NPOINT + 0*NPOINT + t] = cx;
            out[b*3*NPOINT + 1*NPOINT + t] = cy;
            out[b*3*NPOINT + 2*NPOINT + t] = cz;
        }
    }
}

// ---------------- kNN: one warp per query, streaming top-32 -------------
__device__ __forceinline__ void warp_argmax(float& mv, int& ml){
#pragma unroll
    for (int off=16; off; off>>=1){
        float ov = __shfl_xor_sync(0xffffffffu, mv, off);
        int   ol = __shfl_xor_sync(0xffffffffu, ml, off);
        if (ov > mv || (ov == mv && ol < ml)){ mv = ov; ml = ol; }
    }
}

__global__ void __launch_bounds__(256)
knn_kernel(const float* __restrict__ xyz){
    int wid  = threadIdx.x >> 5, lane = threadIdx.x & 31;
    int b = blockIdx.x >> 7;
    int s = ((blockIdx.x & 127) << 3) + wid;
    const float* xb  = xyz + b*NN*3;
    const float* pnb = g_pn + b*NN;

    int qidx = g_fps[b*NPOINT + s];
    float qx = xb[3*qidx], qy = xb[3*qidx+1], qz = xb[3*qidx+2];
    float qn = pnb[qidx];

    float v; int vi;
    {
        int j = lane;
        float dot = __fadd_rn(__fadd_rn(__fmul_rn(qx,xb[3*j]), __fmul_rn(qy,xb[3*j+1])),
                              __fmul_rn(qz,xb[3*j+2]));
        v  = __fadd_rn(__fadd_rn(__fmul_rn(-2.f,dot), qn), pnb[j]);
        vi = j;
    }
    float mv = v; int ml = lane;
    warp_argmax(mv, ml);
    float tau = mv; int maxlane = ml;

    for (int base=32; base<NN; base+=32){
        int j = base + lane;
        float dot = __fadd_rn(__fadd_rn(__fmul_rn(qx,xb[3*j]), __fmul_rn(qy,xb[3*j+1])),
                              __fmul_rn(qz,xb[3*j+2]));
        float cand = __fadd_rn(__fadd_rn(__fmul_rn(-2.f,dot), qn), pnb[j]);
        unsigned mask = __ballot_sync(0xffffffffu, cand < tau);
        while (mask){
            int src  = __ffs(mask) - 1;
            float cv = __shfl_sync(0xffffffffu, cand, src);
            if (lane == maxlane){ v = cv; vi = base + src; }
            if (lane == src) cand = 3.0e38f;
            mv = v; ml = lane;
            warp_argmax(mv, ml);
            tau = mv; maxlane = ml;
            mask = __ballot_sync(0xffffffffu, cand < tau);
        }
    }
    g_knn[(b*NPOINT + s)*KK + lane] = vi;
}

// ---------------- gather-count histogram (int atomics: deterministic) ----
__global__ void zerocnt_kernel(){
    int i = blockIdx.x*blockDim.x + threadIdx.x;
    if (i < UR) g_cnt[i] = 0;
}
__global__ void hist_kernel(){
    int e = blockIdx.x*blockDim.x + threadIdx.x;
    if (e < RR){
        int b = e >> 15;                 // 32768 entries per batch
        atomicAdd(&g_cnt[(b<<12) + g_knn[e]], 1);
    }
}

// ---------------- conv on UNIQUE rows: y[r][o] = sum_c x[r][c]*W[o][c] ---
// 128 rows x 64 outs per block, 128 thr, 8x8/thr. Weighted stats via cnt.
#define CONV_SMEM ((64*72 + 128*65)*4)

template<int MODE>
__global__ void __launch_bounds__(128)
conv_kernel(int i0, int i1, const float* __restrict__ W,
            const float* __restrict__ features, int oid, int affA, int affB){
    extern __shared__ float sm[];
    float* Wt = sm;            // [64][72]
    float* As = sm + 64*72;    // [128][65]

    const int tid = threadIdx.x;
    const int rbase = blockIdx.x * 128;

    for (int i = tid; i < 4096; i += 128){
        int o = i >> 6, c = i & 63;
        Wt[c*72 + o] = W[i];
    }
    for (int i = tid; i < 8192; i += 128){
        int row = i >> 6, c = i & 63;
        int r = rbase + row;
        float vv;
        if (MODE == 0){
            vv = features[(size_t)r*CC + c];          // unique rows: linear!
        } else {
            float x0 = g_buf[i0][(size_t)r*CC + c];
            float a1 = g_aff[affB][0][c], d1 = g_aff[affB][1][c];
            if (MODE == 1){
                vv = leaky(fmaf(a1, x0, d1));
            } else {
                float x1 = g_buf[i1][(size_t)r*CC + c];
                float a0 = g_aff[affA][0][c], d0 = g_aff[affA][1][c];
                vv = leaky(fmaf(a1, x0, d1) + leaky(fmaf(a0, x1, d0)));
            }
        }
        As[row*65 + c] = vv;
    }
    __syncthreads();

    const int ry = tid >> 3, ox = tid & 7;
    const int r0 = ry*8, o0 = ox*8;

    float acc[8][8];
#pragma unroll
    for (int j=0;j<8;++j)
#pragma unroll
        for (int o=0;o<8;++o) acc[j][o] = 0.f;

#pragma unroll 2
    for (int c=0;c<CC;++c){
        float4 w0 = *(const float4*)&Wt[c*72 + o0];
        float4 w1 = *(const float4*)&Wt[c*72 + o0 + 4];
        float av[8];
#pragma unroll
        for (int j=0;j<8;++j) av[j] = As[(r0+j)*65 + c];
#pragma unroll
        for (int j=0;j<8;++j){
            acc[j][0] = fmaf(av[j], w0.x, acc[j][0]);
            acc[j][1] = fmaf(av[j], w0.y, acc[j][1]);
            acc[j][2] = fmaf(av[j], w0.z, acc[j][2]);
            acc[j][3] = fmaf(av[j], w0.w, acc[j][3]);
            acc[j][4] = fmaf(av[j], w1.x, acc[j][4]);
            acc[j][5] = fmaf(av[j], w1.y, acc[j][5]);
            acc[j][6] = fmaf(av[j], w1.z, acc[j][6]);
            acc[j][7] = fmaf(av[j], w1.w, acc[j][7]);
        }
    }

    float* outb = g_buf[oid];
    float cw[8];
#pragma unroll
    for (int j=0;j<8;++j){
        size_t r = (size_t)(rbase + r0 + j);
        cw[j] = (float)__ldg(&g_cnt[r]);
        *(float4*)&outb[r*CC + o0]     = make_float4(acc[j][0],acc[j][1],acc[j][2],acc[j][3]);
        *(float4*)&outb[r*CC + o0 + 4] = make_float4(acc[j][4],acc[j][5],acc[j][6],acc[j][7]);
    }

    __syncthreads();
    float* sred1 = sm;           // overlay Wt region: [16][64]
    float* sred2 = sm + 1024;
#pragma unroll
    for (int o=0;o<8;++o){
        float s1 = 0.f, s2 = 0.f;
#pragma unroll
        for (int j=0;j<8;++j){ s1 += cw[j]*acc[j][o]; s2 += cw[j]*acc[j][o]*acc[j][o]; }
        sred1[ry*64 + o0 + o] = s1;
        sred2[ry*64 + o0 + o] = s2;
    }
    __syncthreads();
    if (tid < CC){
        float s1=0.f, s2=0.f;
#pragma unroll
        for (int j=0;j<16;++j){ s1 += sred1[j*64 + tid]; s2 += sred2[j*64 + tid]; }
        g_part[blockIdx.x][0][tid] = s1;
        g_part[blockIdx.x][1][tid] = s2;
    }
}

// ---------------- BN affine finalize (256 partials) ----------------
__global__ void __launch_bounds__(256)
affine_kernel(int stage, const float* __restrict__ gam, const float* __restrict__ bet){
    __shared__ float r1[256], r2[256];
    int c = blockIdx.x, t = threadIdx.x;
    float s1 = g_part[t][0][c];
    float s2 = g_part[t][1][c];
    r1[t]=s1; r2[t]=s2; __syncthreads();
    for (int off=128; off; off>>=1){
        if (t < off){ r1[t]+=r1[t+off]; r2[t]+=r2[t+off]; }
        __syncthreads();
    }
    if (t==0){
        float inv  = 1.f/(float)RR;
        float mean = r1[0]*inv;
        float var  = r2[0]*inv - mean*mean;
        float a    = gam[c]/sqrtf(var + EPSBN);
        g_aff[stage][0][c] = a;
        g_aff[stage][1][c] = bet[c] - a*mean;
    }
}

// ---------------- x1 on unique rows (pointwise) ----------------
__global__ void __launch_bounds__(256)
x1_kernel(){
    int i = blockIdx.x*blockDim.x + threadIdx.x;   // [0, UR*CC)
    int c = i & 63;
    float a0=g_aff[0][0][c], d0=g_aff[0][1][c];
    float a2=g_aff[2][0][c], d2=g_aff[2][1][c];
    float a4=g_aff[4][0][c], d4=g_aff[4][1][c];
    float xt = leaky(fmaf(a0, g_buf[0][i], d0));
    float x0 = leaky(fmaf(a2, g_buf[2][i], d2) + xt);
    float x1 = leaky(fmaf(a4, g_buf[3][i], d4) + x0);
    g_buf[1][i] = x1;                               // buf1 now holds x1
}

// ---------------- final: gather x1 + max over K (1 query/block) ---------
__global__ void __launch_bounds__(256)
final_kernel(float* __restrict__ out){
    __shared__ float sfin[4][CC];
    int m = blockIdx.x;
    int tid = threadIdx.x;
    int kk = tid >> 6, c = tid & 63;
    int b = m >> 10, s = m & 1023;
    const int* kn = &g_knn[m*KK];
    const float* x1 = g_buf[1];
    size_t bbase = (size_t)b << 12;
    float vmax = -3.4e38f;
#pragma unroll
    for (int j=0;j<8;++j){
        int idx = __ldg(&kn[kk*8 + j]);
        vmax = fmaxf(vmax, x1[(bbase + idx)*CC + c]);
    }
    sfin[kk][c] = vmax;
    __syncthreads();
    if (tid < CC){
        float v = fmaxf(fmaxf(sfin[0][tid], sfin[1][tid]),
                        fmaxf(sfin[2][tid], sfin[3][tid]));
        out[BB*3*NPOINT + (b*CC + tid)*NPOINT + s] = v;
    }
}

// ---------------- launch ----------------
extern "C" void kernel_launch(void* const* d_in, const int* in_sizes, int n_in,
                              void* d_out, int out_size){
    (void)n_in; (void)out_size;
    const float* xyz  = (const float*)d_in[0];
    const float* feat = (const float*)d_in[1];
    const float *w[5], *gam[5], *bet[5];
    if (in_sizes[3] == CC*CC){
        const int wi[5]={2,3,4,5,6}, gi[5]={12,13,14,15,16}, bi[5]={17,18,19,20,21};
        for (int i=0;i<5;++i){ w[i]=(const float*)d_in[wi[i]];
                               gam[i]=(const float*)d_in[gi[i]];
                               bet[i]=(const float*)d_in[bi[i]]; }
    } else {
        const int wi[5]={2,6,10,14,18}, gi[5]={4,8,12,16,20}, bi[5]={5,9,13,17,21};
        for (int i=0;i<5;++i){ w[i]=(const float*)d_in[wi[i]];
                               gam[i]=(const float*)d_in[gi[i]];
                               bet[i]=(const float*)d_in[bi[i]]; }
    }
    float* out = (float*)d_out;

    cudaFuncSetAttribute(conv_kernel<0>, cudaFuncAttributeMaxDynamicSharedMemorySize, CONV_SMEM);
    cudaFuncSetAttribute(conv_kernel<1>, cudaFuncAttributeMaxDynamicSharedMemorySize, CONV_SMEM);
    cudaFuncSetAttribute(conv_kernel<2>, cudaFuncAttributeMaxDynamicSharedMemorySize, CONV_SMEM);

    pnorm_kernel<<<128,256>>>(xyz);
    fps_kernel<<<BB,256>>>(xyz, out);
    knn_kernel<<<1024,256>>>(xyz);
    zerocnt_kernel<<<32,1024>>>();
    hist_kernel<<<256,1024>>>();

    conv_kernel<0><<<256,128,CONV_SMEM>>>(0,0,w[0],feat,0,0,0);
    affine_kernel<<<64,256>>>(0, gam[0], bet[0]);
    conv_kernel<1><<<256,128,CONV_SMEM>>>(0,0,w[1],feat,1,0,0);
    affine_kernel<<<64,256>>>(1, gam[1], bet[1]);
    conv_kernel<1><<<256,128,CONV_SMEM>>>(1,0,w[2],feat,2,0,1);
    affine_kernel<<<64,256>>>(2, gam[2], bet[2]);
    conv_kernel<2><<<256,128,CONV_SMEM>>>(2,0,w[3],feat,1,0,2);
    affine_kernel<<<64,256>>>(3, gam[3], bet[3]);
    conv_kernel<1><<<256,128,CONV_SMEM>>>(1,0,w[4],feat,3,0,3);
    affine_kernel<<<64,256>>>(4, gam[4], bet[4]);

    x1_kernel<<<8192,256>>>();
    final_kernel<<<MM,256>>>(out);
}